// round 16
// baseline (speedup 1.0000x reference)
#include <cuda_runtime.h>
#include <cstdint>

#define NB 16
#define NO 64
#define LOCS 1024
#define KVOL 576                 // 64 ch * 3 * 3
#define NSTG 9                   // 9 stages x 4KB (16 rows x 256B each)
#define NSLOT 4                  // ring slots per warp

#define SMEM_B_BYTES (288 * 16 * 8)       // 36864: B tf32 slots (stride-16, swz)
#define SMEM_W_BYTES (4 * NSLOT * 4096)   // 65536: 4 warps x 4 slots x 4KB
#define SMEM_TOTAL   (SMEM_B_BYTES + SMEM_W_BYTES)   // 102400 -> 2 CTAs/SM

__device__ float g_xT[64 * 32 * 32 * NB];          // (c,h,w,b), 4 MB
__device__ float g_ps[64 * NO], g_ps2[64 * NO];    // bucketed BN partials
__device__ float g_scale[NO], g_shift[NO];

__device__ __forceinline__ uint32_t tf32_rna(float f) {
    uint32_t u;
    asm("cvt.rna.tf32.f32 %0, %1;" : "=r"(u) : "f"(f));
    return u;
}
__device__ __forceinline__ void mma_tf32(float* d, const uint32_t* a, uint32_t b0,
                                         uint32_t b1) {
    asm volatile(
        "mma.sync.aligned.m16n8k8.row.col.f32.tf32.tf32.f32 "
        "{%0,%1,%2,%3}, {%4,%5,%6,%7}, {%8,%9}, {%0,%1,%2,%3};"
        : "+f"(d[0]), "+f"(d[1]), "+f"(d[2]), "+f"(d[3])
        : "r"(a[0]), "r"(a[1]), "r"(a[2]), "r"(a[3]), "r"(b0), "r"(b1));
}
__device__ __forceinline__ void cp16(void* dst_smem, const void* src) {
    unsigned d = (unsigned)__cvta_generic_to_shared(dst_smem);
    asm volatile("cp.async.ca.shared.global [%0], [%1], 16;" :: "r"(d), "l"(src));
}
#define CP_COMMIT() asm volatile("cp.async.commit_group;")
#define CP_WAIT2()  asm volatile("cp.async.wait_group 2;")

// ---------------------------------------------------------------------------
// x (b,c,h,w) -> xT (c,h,w,b); first 16 blocks also zero the BN partials.
// ---------------------------------------------------------------------------
__global__ __launch_bounds__(256) void transpose_kernel(const float* __restrict__ x) {
    int idx = blockIdx.x * 256 + threadIdx.x;
    if (blockIdx.x < 16) { g_ps[idx] = 0.f; g_ps2[idx] = 0.f; }
    int b = idx & 15, w = (idx >> 4) & 31, h = (idx >> 9) & 31, c = idx >> 14;
    g_xT[idx] = x[(((b << 6) + c) << 10) + (h << 5) + w];
}

// ---------------------------------------------------------------------------
// One CTA (128 thr, 4 warps) per output location.
// D[64 x 16] = W_loc[64 x 576] * X_loc[576 x 16], mma.sync tf32 (operands
// single tf32-RNA; rel err ~3e-4 < 1e-3).
//
// W: per-warp 4-slot ring (R12 geometry, depth doubled). Stage = 16 rows x
// 256B (4 kb); fill instruction = 2 rows x 256B contiguous (lane L: row
// rhalf=L>>4, 16B chunk L&15). wait_group 2 keeps 3 stages (12KB/warp) in
// flight during consume (R12 kept 1). Slot layout: row r at r*256, 64B-block
// swizzle blk' = blk ^ (r&3) -> fill-STS and LDS.128 consume conflict-free.
// B slot (kpair kp, col n): 8B at 8*(kp*16 + ((n+2kp)&15)) [validated].
// ---------------------------------------------------------------------------
__global__ __launch_bounds__(128, 2) void conv_mma_kernel(const float* __restrict__ wgt,
                                                          const float* __restrict__ bias,
                                                          float* __restrict__ out) {
    extern __shared__ uint32_t bsm[];                // B fragments (36864 B)
    char* wsm = (char*)bsm + SMEM_B_BYTES;           // W rings
    const int tid = threadIdx.x, wid = tid >> 5, lane = tid & 31;
    const int tg = lane & 3, g = lane >> 2;
    const int loc = blockIdx.x, li = loc >> 5, lj = loc & 31;

    char* wring = wsm + (wid << 14);                 // this warp's 4 x 4KB
    // Fill geometry (R12-validated): lane -> row half + 16B chunk of 256B.
    const int rhalf = lane >> 4;                     // 0/1
    const int koff = lane & 15;                      // 16B chunk within 256B
    const int kbl_f = (lane >> 2) & 3;               // kb-block of this chunk
    const float* src0 = wgt + ((size_t)((wid << 4) + rhalf) * LOCS + loc) * KVOL
                      + (koff << 2);
    char* dst0 = wring + (rhalf << 8) + ((lane & 3) << 4);

#define FILL_STAGE(st, ss)                                                     \
    _Pragma("unroll")                                                          \
    for (int i = 0; i < 8; i++) {                                              \
        int swz = ((kbl_f ^ (((i & 1) << 1) + rhalf)) & 3) << 6;               \
        cp16(dst0 + ((ss) << 12) + (i << 9) + swz,                             \
             src0 + (size_t)i * (2 * LOCS * KVOL) + (st) * 64);                \
    }

    // Prologue: 3 stages in flight.
    FILL_STAGE(0, 0); CP_COMMIT();
    FILL_STAGE(1, 1); CP_COMMIT();
    FILL_STAGE(2, 2); CP_COMMIT();

    // ---- Stage B = X tf32 fragments (stride-16 swizzled slots) ----
    for (int t = tid; t < 288 * 4; t += 128) {
        int kp = t >> 2, nq = t & 3;                 // kpair, n-quad
        float4 xq[2];
#pragma unroll
        for (int h = 0; h < 2; h++) {
            int k = 2 * kp + h;
            int c = k / 9, r = k - c * 9, p = r / 3, q = r - p * 3;
            int ih = li + p - 1, iw = lj + q - 1;
            xq[h] = make_float4(0.f, 0.f, 0.f, 0.f);
            if ((unsigned)ih < 32u && (unsigned)iw < 32u)
                xq[h] = *(const float4*)&g_xT[(((((c << 5) + ih) << 5) + iw) << 4) + (nq << 2)];
        }
        const float* x0 = &xq[0].x;
        const float* x1 = &xq[1].x;
#pragma unroll
        for (int e = 0; e < 4; e++) {
            int n = (nq << 2) + e;
            uint32_t idx = ((uint32_t)(kp << 4) + (uint32_t)((n + 2 * kp) & 15)) << 1;
            bsm[idx] = tf32_rna(x0[e]);
            bsm[idx + 1] = tf32_rna(x1[e]);
        }
    }
    __syncthreads();

    // ---- Main loop: 9 stages x 4 kb ----
    float d[2][4] = {{0.f, 0.f, 0.f, 0.f}, {0.f, 0.f, 0.f, 0.f}};

    for (int st = 0; st < NSTG; st++) {
        CP_WAIT2();                                   // stage st complete
        __syncwarp();
        const char* ap = wring + ((st & 3) << 12) + (tg << 4);
#pragma unroll
        for (int kbl = 0; kbl < 4; kbl++) {
            int sw = ((kbl ^ g) & 3) << 6;            // (g+8)&3 == g&3
            float4 A0 = *(const float4*)(ap + (g << 8) + sw);
            float4 A1 = *(const float4*)(ap + ((g + 8) << 8) + sw);
            int kb = (st << 2) + kbl;
#pragma unroll
            for (int s = 0; s < 2; s++) {
                uint32_t aa[4];
                aa[0] = tf32_rna(s ? A0.z : A0.x);
                aa[1] = tf32_rna(s ? A1.z : A1.x);
                aa[2] = tf32_rna(s ? A0.w : A0.y);
                aa[3] = tf32_rna(s ? A1.w : A1.y);
                int kp = (kb << 3) + (tg << 1) + s;
#pragma unroll
                for (int nt = 0; nt < 2; nt++) {
                    int n = g + (nt << 3);
                    uint2 q = *(const uint2*)&bsm[((uint32_t)(kp << 4)
                                  + (uint32_t)((n + 2 * kp) & 15)) << 1];
                    mma_tf32(d[nt], aa, q.x, q.y);
                }
            }
        }
        __syncwarp();                                 // slot fully read
        if (st + 3 < NSTG) { FILL_STAGE(st + 3, (st + 3) & 3); }
        CP_COMMIT();                                  // uniform: 1 group/stage
    }

    // ---- Epilogue: lane (g,tg) holds rows o0=16wid+g, o1=o0+8;
    //      cols b = 8nt + 2tg + {0,1}. ----
    int o0 = (wid << 4) + g, o1 = o0 + 8;
    float bv0 = bias[(o0 << 10) + loc];
    float bv1 = bias[(o1 << 10) + loc];
    float s0 = 0.f, q0 = 0.f, s1 = 0.f, q1 = 0.f;
#pragma unroll
    for (int nt = 0; nt < 2; nt++) {
#pragma unroll
        for (int e = 0; e < 2; e++) {
            int b = (nt << 3) + (tg << 1) + e;
            float v0 = d[nt][e] + bv0;
            float v1 = d[nt][e + 2] + bv1;
            out[(((b << 6) + o0) << 10) + loc] = v0;
            out[(((b << 6) + o1) << 10) + loc] = v1;
            s0 += v0; q0 = fmaf(v0, v0, q0);
            s1 += v1; q1 = fmaf(v1, v1, q1);
        }
    }
#pragma unroll
    for (int m = 1; m < 4; m <<= 1) {
        s0 += __shfl_down_sync(0xffffffffu, s0, m, 4);
        q0 += __shfl_down_sync(0xffffffffu, q0, m, 4);
        s1 += __shfl_down_sync(0xffffffffu, s1, m, 4);
        q1 += __shfl_down_sync(0xffffffffu, q1, m, 4);
    }
    if (tg == 0) {
        int bkt = loc & 63;
        atomicAdd(&g_ps[(bkt << 6) + o0], s0);
        atomicAdd(&g_ps2[(bkt << 6) + o0], q0);
        atomicAdd(&g_ps[(bkt << 6) + o1], s1);
        atomicAdd(&g_ps2[(bkt << 6) + o1], q1);
    }
}

// ---------------------------------------------------------------------------
__global__ void params_kernel(const float* __restrict__ gamma,
                              const float* __restrict__ beta) {
    int o = threadIdx.x;
    float S = 0.f, S2 = 0.f;
    for (int k = 0; k < 64; k++) { S += g_ps[(k << 6) + o]; S2 += g_ps2[(k << 6) + o]; }
    const float inv = 1.f / (float)(NB * LOCS);
    float mean = S * inv;
    float var = S2 * inv - mean * mean;              // biased variance (ddof=0)
    float sc = gamma[o] * rsqrtf(var + 1e-5f);
    g_scale[o] = sc;
    g_shift[o] = beta[o] - mean * sc;
}

__global__ __launch_bounds__(256) void finalize_kernel(float* __restrict__ y) {
    int idx = blockIdx.x * 256 + threadIdx.x;
    int o = (idx >> 8) & 63;
    float sc = g_scale[o], sh = g_shift[o];
    float4 v = ((float4*)y)[idx];
    v.x = fmaxf(fmaf(v.x, sc, sh), 0.f);
    v.y = fmaxf(fmaf(v.y, sc, sh), 0.f);
    v.z = fmaxf(fmaf(v.z, sc, sh), 0.f);
    v.w = fmaxf(fmaf(v.w, sc, sh), 0.f);
    ((float4*)y)[idx] = v;
}

extern "C" void kernel_launch(void* const* d_in, const int* in_sizes, int n_in,
                              void* d_out, int out_size) {
    const float* x     = (const float*)d_in[0];
    const float* w     = (const float*)d_in[1];
    const float* bias  = (const float*)d_in[2];
    const float* gamma = (const float*)d_in[3];
    const float* beta  = (const float*)d_in[4];
    float* out = (float*)d_out;

    cudaFuncSetAttribute(conv_mma_kernel, cudaFuncAttributeMaxDynamicSharedMemorySize,
                         SMEM_TOTAL);

    transpose_kernel<<<4096, 256>>>(x);                  // + zero BN partials
    conv_mma_kernel<<<1024, 128, SMEM_TOTAL>>>(w, bias, out);
    params_kernel<<<1, 64>>>(gamma, beta);
    finalize_kernel<<<1024, 256>>>(out);
}

// round 17
// speedup vs baseline: 1.1150x; 1.1150x over previous
#include <cuda_runtime.h>
#include <cstdint>

#define NB 16
#define NO 64
#define LOCS 1024
#define KVOL 576                 // 64 ch * 3 * 3
#define NKB 36                   // 16-k blocks

#define BSLOT_STRIDE 18                       // slots of 8B per kpair row
#define SMEM_B_BYTES (288 * BSLOT_STRIDE * 8) // 41472: B tf32 fragment slots
#define SMEM_W_BYTES (4 * 2 * 4096)           // 32768: 4 warps x 2 slots x 4KB
#define SMEM_TOTAL   (SMEM_B_BYTES + SMEM_W_BYTES)   // 74240 -> 3 CTAs/SM

__device__ float g_xT[64 * 32 * 32 * NB];          // (c,h,w,b), 4 MB
__device__ float g_ps[64 * NO], g_ps2[64 * NO];    // bucketed BN partials
__device__ float g_scale[NO], g_shift[NO];

__device__ __forceinline__ uint32_t tf32_rna(float f) {
    uint32_t u;
    asm("cvt.rna.tf32.f32 %0, %1;" : "=r"(u) : "f"(f));
    return u;
}
__device__ __forceinline__ void mma_tf32(float* d, const uint32_t* a, uint32_t b0,
                                         uint32_t b1) {
    asm volatile(
        "mma.sync.aligned.m16n8k8.row.col.f32.tf32.tf32.f32 "
        "{%0,%1,%2,%3}, {%4,%5,%6,%7}, {%8,%9}, {%0,%1,%2,%3};"
        : "+f"(d[0]), "+f"(d[1]), "+f"(d[2]), "+f"(d[3])
        : "r"(a[0]), "r"(a[1]), "r"(a[2]), "r"(a[3]), "r"(b0), "r"(b1));
}
__device__ __forceinline__ void cp16(void* dst_smem, const void* src) {
    unsigned d = (unsigned)__cvta_generic_to_shared(dst_smem);
    asm volatile("cp.async.ca.shared.global [%0], [%1], 16;" :: "r"(d), "l"(src));
}
#define CP_COMMIT() asm volatile("cp.async.commit_group;")
#define CP_WAIT1()  asm volatile("cp.async.wait_group 1;")

// ---------------------------------------------------------------------------
// Coalesced transpose: one CTA per (c,h). Read sweeps w (128B/warp-instr),
// write sweeps (w,b) (contiguous 1KB runs). smem tile [16][33] kills bank
// conflicts both phases. First 16 blocks also zero the BN partials.
// ---------------------------------------------------------------------------
__global__ __launch_bounds__(256) void transpose_kernel(const float* __restrict__ x) {
    __shared__ float tile[16 * 33];
    int tid = threadIdx.x;
    if (blockIdx.x < 16) {
        int z = (blockIdx.x << 8) + tid;
        g_ps[z] = 0.f;
        g_ps2[z] = 0.f;
    }
    int c = blockIdx.x >> 5, h = blockIdx.x & 31;

#pragma unroll
    for (int rep = 0; rep < 2; rep++) {
        int i = (rep << 8) + tid;                   // over (b, w), w fastest
        int w = i & 31, b = i >> 5;
        tile[b * 33 + w] = x[(b << 16) + (c << 10) + (h << 5) + w];
    }
    __syncthreads();
#pragma unroll
    for (int rep = 0; rep < 2; rep++) {
        int i = (rep << 8) + tid;                   // over (w, b), b fastest
        int b = i & 15, w = i >> 4;
        g_xT[(((((c << 5) + h) << 5) + w) << 4) + b] = tile[b * 33 + w];
    }
}

// ---------------------------------------------------------------------------
// One CTA (128 thr, 4 warps) per output location.  [R12 — best known]
// D[64 x 16] = W_loc[64 x 576] * X_loc[576 x 16], mma.sync tf32 (operands
// single tf32-RNA; rel err ~3e-4 < 1e-3).
// W: per-warp 2-slot ring; stage = 16 rows x 256B, fill instruction = 2 rows
// x 256B contiguous. B slot (kpair kp, col n): 8B at 8*(kp*18 + n).
// ---------------------------------------------------------------------------
__global__ __launch_bounds__(128, 3) void conv_mma_kernel(const float* __restrict__ wgt,
                                                          const float* __restrict__ bias,
                                                          float* __restrict__ out) {
    extern __shared__ uint32_t bsm[];                // B fragments
    char* wsm = (char*)bsm + SMEM_B_BYTES;           // W pipeline
    const int tid = threadIdx.x, wid = tid >> 5, lane = tid & 31;
    const int tg = lane & 3, g = lane >> 2;
    const int loc = blockIdx.x, li = loc >> 5, lj = loc & 31;

    // Fill geometry: lane -> row half (2 rows/instr) + 16B chunk of 256B.
    const int rhalf = lane >> 4;
    const int koff = lane & 15;
    const int kbl_f = (lane >> 2) & 3;
    const float* src0 = wgt + ((size_t)((wid << 4) + rhalf) * LOCS + loc) * KVOL
                      + (koff << 2);
    char* dst0 = wsm + (wid << 13) + (rhalf << 8) + ((lane & 3) << 4);

#define FILL_STAGE(st, ss)                                                     \
    _Pragma("unroll")                                                          \
    for (int i = 0; i < 8; i++) {                                              \
        int swz = ((kbl_f ^ (((i & 1) << 1) + rhalf)) & 3) << 6;               \
        cp16(dst0 + ((ss) << 12) + (i << 9) + swz,                             \
             src0 + (size_t)i * (2 * LOCS * KVOL) + (st) * 64);                \
    }

    FILL_STAGE(0, 0); CP_COMMIT();
    FILL_STAGE(1, 1); CP_COMMIT();

    // ---- Stage B = X tf32 fragments ----
    for (int t = tid; t < 288 * 4; t += 128) {
        int kp = t >> 2, nq = t & 3;
        float4 xq[2];
#pragma unroll
        for (int h = 0; h < 2; h++) {
            int k = 2 * kp + h;
            int c = k / 9, r = k - c * 9, p = r / 3, q = r - p * 3;
            int ih = li + p - 1, iw = lj + q - 1;
            xq[h] = make_float4(0.f, 0.f, 0.f, 0.f);
            if ((unsigned)ih < 32u && (unsigned)iw < 32u)
                xq[h] = *(const float4*)&g_xT[(((((c << 5) + ih) << 5) + iw) << 4) + (nq << 2)];
        }
        const float* x0 = &xq[0].x;
        const float* x1 = &xq[1].x;
#pragma unroll
        for (int e = 0; e < 4; e++) {
            int n = (nq << 2) + e;
            uint32_t idx = ((uint32_t)(kp * BSLOT_STRIDE) + (uint32_t)((n + 2 * kp) & 15)) << 1;
            bsm[idx] = tf32_rna(x0[e]);
            bsm[idx + 1] = tf32_rna(x1[e]);
        }
    }
    __syncthreads();

    // ---- Main loop: 9 stages x 4 kb ----
    float d[2][4] = {{0.f, 0.f, 0.f, 0.f}, {0.f, 0.f, 0.f, 0.f}};
    const char* wcons = wsm + (wid << 13) + (tg << 4);

    for (int st = 0; st < 9; st++) {
        CP_WAIT1();
        __syncwarp();
        const char* ap = wcons + ((st & 1) << 12);
#pragma unroll
        for (int kbl = 0; kbl < 4; kbl++) {
            int sw = ((kbl ^ g) & 3) << 6;
            float4 A0 = *(const float4*)(ap + (g << 8) + sw);
            float4 A1 = *(const float4*)(ap + ((g + 8) << 8) + sw);
            int kb = (st << 2) + kbl;
#pragma unroll
            for (int s = 0; s < 2; s++) {
                uint32_t aa[4];
                aa[0] = tf32_rna(s ? A0.z : A0.x);
                aa[1] = tf32_rna(s ? A1.z : A1.x);
                aa[2] = tf32_rna(s ? A0.w : A0.y);
                aa[3] = tf32_rna(s ? A1.w : A1.y);
                int kp = (kb << 3) + (tg << 1) + s;
#pragma unroll
                for (int nt = 0; nt < 2; nt++) {
                    int n = g + (nt << 3);
                    uint2 q = *(const uint2*)&bsm[((uint32_t)(kp * BSLOT_STRIDE)
                                  + (uint32_t)((n + 2 * kp) & 15)) << 1];
                    mma_tf32(d[nt], aa, q.x, q.y);
                }
            }
        }
        __syncwarp();
        if (st + 2 < 9) { FILL_STAGE(st + 2, st & 1); }
        CP_COMMIT();
    }

    // ---- Epilogue ----
    int o0 = (wid << 4) + g, o1 = o0 + 8;
    float bv0 = bias[(o0 << 10) + loc];
    float bv1 = bias[(o1 << 10) + loc];
    float s0 = 0.f, q0 = 0.f, s1 = 0.f, q1 = 0.f;
#pragma unroll
    for (int nt = 0; nt < 2; nt++) {
#pragma unroll
        for (int e = 0; e < 2; e++) {
            int b = (nt << 3) + (tg << 1) + e;
            float v0 = d[nt][e] + bv0;
            float v1 = d[nt][e + 2] + bv1;
            out[(((b << 6) + o0) << 10) + loc] = v0;
            out[(((b << 6) + o1) << 10) + loc] = v1;
            s0 += v0; q0 = fmaf(v0, v0, q0);
            s1 += v1; q1 = fmaf(v1, v1, q1);
        }
    }
#pragma unroll
    for (int m = 1; m < 4; m <<= 1) {
        s0 += __shfl_down_sync(0xffffffffu, s0, m, 4);
        q0 += __shfl_down_sync(0xffffffffu, q0, m, 4);
        s1 += __shfl_down_sync(0xffffffffu, s1, m, 4);
        q1 += __shfl_down_sync(0xffffffffu, q1, m, 4);
    }
    if (tg == 0) {
        int bkt = loc & 63;
        atomicAdd(&g_ps[(bkt << 6) + o0], s0);
        atomicAdd(&g_ps2[(bkt << 6) + o0], q0);
        atomicAdd(&g_ps[(bkt << 6) + o1], s1);
        atomicAdd(&g_ps2[(bkt << 6) + o1], q1);
    }
}

// ---------------------------------------------------------------------------
__global__ void params_kernel(const float* __restrict__ gamma,
                              const float* __restrict__ beta) {
    int o = threadIdx.x;
    float S = 0.f, S2 = 0.f;
    for (int k = 0; k < 64; k++) { S += g_ps[(k << 6) + o]; S2 += g_ps2[(k << 6) + o]; }
    const float inv = 1.f / (float)(NB * LOCS);
    float mean = S * inv;
    float var = S2 * inv - mean * mean;              // biased variance (ddof=0)
    float sc = gamma[o] * rsqrtf(var + 1e-5f);
    g_scale[o] = sc;
    g_shift[o] = beta[o] - mean * sc;
}

__global__ __launch_bounds__(256) void finalize_kernel(float* __restrict__ y) {
    int idx = blockIdx.x * 256 + threadIdx.x;
    int o = (idx >> 8) & 63;
    float sc = g_scale[o], sh = g_shift[o];
    float4 v = ((float4*)y)[idx];
    v.x = fmaxf(fmaf(v.x, sc, sh), 0.f);
    v.y = fmaxf(fmaf(v.y, sc, sh), 0.f);
    v.z = fmaxf(fmaf(v.z, sc, sh), 0.f);
    v.w = fmaxf(fmaf(v.w, sc, sh), 0.f);
    ((float4*)y)[idx] = v;
}

extern "C" void kernel_launch(void* const* d_in, const int* in_sizes, int n_in,
                              void* d_out, int out_size) {
    const float* x     = (const float*)d_in[0];
    const float* w     = (const float*)d_in[1];
    const float* bias  = (const float*)d_in[2];
    const float* gamma = (const float*)d_in[3];
    const float* beta  = (const float*)d_in[4];
    float* out = (float*)d_out;

    cudaFuncSetAttribute(conv_mma_kernel, cudaFuncAttributeMaxDynamicSharedMemorySize,
                         SMEM_TOTAL);

    transpose_kernel<<<2048, 256>>>(x);                  // + zero BN partials
    conv_mma_kernel<<<1024, 128, SMEM_TOTAL>>>(w, bias, out);
    params_kernel<<<1, 64>>>(gamma, beta);
    finalize_kernel<<<1024, 256>>>(out);
}